// round 1
// baseline (speedup 1.0000x reference)
#include <cuda_runtime.h>
#include <math.h>

#define BB 8
#define LLEN 1024
#define DMODEL 1024
#define NH 16
#define DHEAD 64

// ---------------- static scratch (no allocations allowed) ----------------
static __device__ float g_Q[(size_t)BB * NH * LLEN * DHEAD];     // 32 MB
static __device__ float g_K[(size_t)BB * NH * LLEN * DHEAD];     // 32 MB
static __device__ float g_V[(size_t)BB * NH * LLEN * DHEAD];     // 32 MB
static __device__ float g_ctx[(size_t)BB * LLEN * DMODEL];       // 32 MB
static __device__ float g_proj[(size_t)BB * LLEN * DMODEL];      // 32 MB
static __device__ float g_attn[(size_t)BB * NH * LLEN * LLEN];   // 512 MB fallback

// =========================================================================
// Kernel 1: fused QKV projection.  Y = X @ [Wq | Wk | Wv], scattered into
// head-major [B,H,L,d] layout.  M=8192, N=3072, K=1024.
// BM=BN=128, BK=8, 256 threads, 8x8 microtile.
// =========================================================================
__global__ void qkv_gemm_kernel(const float* __restrict__ X,
                                const float* __restrict__ Wq,
                                const float* __restrict__ Wk,
                                const float* __restrict__ Wv)
{
    __shared__ float As[8][132];
    __shared__ float Bs[8][132];

    const int tid = threadIdx.x;
    const int tx = tid & 15;
    const int ty = tid >> 4;

    const int ng = blockIdx.x * 128;      // global col in [0,3072)
    const int wsel = ng / DMODEL;         // 0=Q 1=K 2=V
    const int n0 = ng % DMODEL;
    const float* __restrict__ W = (wsel == 0) ? Wq : (wsel == 1 ? Wk : Wv);
    const int m0 = blockIdx.y * 128;

    float acc[8][8];
#pragma unroll
    for (int i = 0; i < 8; i++)
#pragma unroll
        for (int j = 0; j < 8; j++) acc[i][j] = 0.f;

    for (int k0 = 0; k0 < DMODEL; k0 += 8) {
#pragma unroll
        for (int r = 0; r < 4; r++) {
            int idx = tid + r * 256;
            int m = idx >> 3, k = idx & 7;
            As[k][m] = X[(size_t)(m0 + m) * DMODEL + k0 + k];
            int kb = idx >> 7, n = idx & 127;
            Bs[kb][n] = W[(size_t)(k0 + kb) * DMODEL + n0 + n];
        }
        __syncthreads();
#pragma unroll
        for (int kk = 0; kk < 8; kk++) {
            float a[8], bv[8];
#pragma unroll
            for (int i = 0; i < 8; i++) a[i] = As[kk][ty * 8 + i];
#pragma unroll
            for (int j = 0; j < 8; j++) bv[j] = Bs[kk][tx * 8 + j];
#pragma unroll
            for (int i = 0; i < 8; i++)
#pragma unroll
                for (int j = 0; j < 8; j++) acc[i][j] += a[i] * bv[j];
        }
        __syncthreads();
    }

    float* __restrict__ dst = (wsel == 0) ? g_Q : (wsel == 1 ? g_K : g_V);
#pragma unroll
    for (int i = 0; i < 8; i++) {
        int m = m0 + ty * 8 + i;
        int b = m >> 10, l = m & 1023;
#pragma unroll
        for (int j = 0; j < 8; j++) {
            int c = n0 + tx * 8 + j;
            int h = c >> 6, d = c & 63;
            dst[(((size_t)(b * NH + h)) * LLEN + l) * DHEAD + d] = acc[i][j];
        }
    }
}

// =========================================================================
// Kernel 2: S = (Q K^T) * scale, then mask -> NEG. 64x64 tiles, K=64 fully
// resident in smem. Writes pre-softmax scores into the attn buffer.
// =========================================================================
__global__ void scores_kernel(const int* __restrict__ mask,
                              float* __restrict__ attn_ext)
{
    __shared__ float Qs[DHEAD][65];
    __shared__ float Ks[DHEAD][65];

    const int bh = blockIdx.z;
    const int b  = bh / NH;
    const int n0 = blockIdx.x * 64;
    const int m0 = blockIdx.y * 64;
    const float* __restrict__ Q = g_Q + (size_t)bh * LLEN * DHEAD;
    const float* __restrict__ K = g_K + (size_t)bh * LLEN * DHEAD;
    const int tid = threadIdx.x;

#pragma unroll
    for (int r = 0; r < 16; r++) {
        int idx = tid + r * 256;
        int m = idx >> 6, d = idx & 63;
        Qs[d][m] = Q[(size_t)(m0 + m) * DHEAD + d];
        Ks[d][m] = K[(size_t)(n0 + m) * DHEAD + d];
    }
    __syncthreads();

    const int tx = tid & 15;
    const int ty = tid >> 4;
    float acc[4][4];
#pragma unroll
    for (int i = 0; i < 4; i++)
#pragma unroll
        for (int j = 0; j < 4; j++) acc[i][j] = 0.f;

#pragma unroll
    for (int d = 0; d < DHEAD; d++) {
        float a[4], bv[4];
#pragma unroll
        for (int i = 0; i < 4; i++) a[i] = Qs[d][ty * 4 + i];
#pragma unroll
        for (int j = 0; j < 4; j++) bv[j] = Ks[d][tx * 4 + j];
#pragma unroll
        for (int i = 0; i < 4; i++)
#pragma unroll
            for (int j = 0; j < 4; j++) acc[i][j] += a[i] * bv[j];
    }

    float* __restrict__ P = attn_ext ? attn_ext : g_attn;
    const float scale = 0.125f;   // 1/sqrt(64)
#pragma unroll
    for (int i = 0; i < 4; i++) {
        int q = m0 + ty * 4 + i;
        const int* mrow = mask + ((size_t)b * LLEN + q) * LLEN;
        float* prow = P + ((size_t)bh * LLEN + q) * LLEN;
#pragma unroll
        for (int j = 0; j < 4; j++) {
            int kcol = n0 + tx * 4 + j;
            float v = acc[i][j] * scale;
            if (mrow[kcol] != 0) v = -1e9f;
            prow[kcol] = v;
        }
    }
}

// =========================================================================
// Kernel 3: in-place row softmax over the attn buffer. One block per row.
// =========================================================================
__global__ void softmax_kernel(float* __restrict__ attn_ext)
{
    float* __restrict__ P = attn_ext ? attn_ext : g_attn;
    const size_t row = blockIdx.x;
    float* __restrict__ prow = P + row * LLEN;
    const int tid = threadIdx.x;

    float4 v = reinterpret_cast<float4*>(prow)[tid];
    float mx = fmaxf(fmaxf(v.x, v.y), fmaxf(v.z, v.w));

    __shared__ float red[8];
#pragma unroll
    for (int o = 16; o > 0; o >>= 1) mx = fmaxf(mx, __shfl_xor_sync(0xffffffffu, mx, o));
    if ((tid & 31) == 0) red[tid >> 5] = mx;
    __syncthreads();
    float m = red[0];
#pragma unroll
    for (int w = 1; w < 8; w++) m = fmaxf(m, red[w]);
    __syncthreads();

    v.x = expf(v.x - m); v.y = expf(v.y - m);
    v.z = expf(v.z - m); v.w = expf(v.w - m);
    float s = v.x + v.y + v.z + v.w;
#pragma unroll
    for (int o = 16; o > 0; o >>= 1) s += __shfl_xor_sync(0xffffffffu, s, o);
    if ((tid & 31) == 0) red[tid >> 5] = s;
    __syncthreads();
    float tot = red[0];
#pragma unroll
    for (int w = 1; w < 8; w++) tot += red[w];

    float inv = 1.0f / tot;
    v.x *= inv; v.y *= inv; v.z *= inv; v.w *= inv;
    reinterpret_cast<float4*>(prow)[tid] = v;
}

// =========================================================================
// Kernel 4: context = P @ V per head.  [1024,1024]@[1024,64].
// BM=128, BN=64, BK=32.  Writes ctx in [B, L, H*dv] layout.
// =========================================================================
__global__ void pv_kernel(const float* __restrict__ attn_ext)
{
    __shared__ float Ps[32][129];
    __shared__ float Vs[32][65];

    const int bh = blockIdx.y;
    const int m0 = blockIdx.x * 128;
    const float* __restrict__ P =
        (attn_ext ? attn_ext : (const float*)g_attn) + (size_t)bh * LLEN * LLEN;
    const float* __restrict__ V = g_V + (size_t)bh * LLEN * DHEAD;
    const int tid = threadIdx.x;
    const int tx = tid & 15;   // n: 16 * 4 = 64
    const int ty = tid >> 4;   // m: 16 * 8 = 128

    float acc[8][4];
#pragma unroll
    for (int i = 0; i < 8; i++)
#pragma unroll
        for (int j = 0; j < 4; j++) acc[i][j] = 0.f;

    for (int k0 = 0; k0 < LLEN; k0 += 32) {
#pragma unroll
        for (int r = 0; r < 16; r++) {
            int idx = tid + r * 256;
            int m = idx >> 5, k = idx & 31;
            Ps[k][m] = P[(size_t)(m0 + m) * LLEN + k0 + k];
        }
#pragma unroll
        for (int r = 0; r < 8; r++) {
            int idx = tid + r * 256;
            int k = idx >> 6, n = idx & 63;
            Vs[k][n] = V[(size_t)(k0 + k) * DHEAD + n];
        }
        __syncthreads();
#pragma unroll
        for (int kk = 0; kk < 32; kk++) {
            float a[8], bv[4];
#pragma unroll
            for (int i = 0; i < 8; i++) a[i] = Ps[kk][ty * 8 + i];
#pragma unroll
            for (int j = 0; j < 4; j++) bv[j] = Vs[kk][tx * 4 + j];
#pragma unroll
            for (int i = 0; i < 8; i++)
#pragma unroll
                for (int j = 0; j < 4; j++) acc[i][j] += a[i] * bv[j];
        }
        __syncthreads();
    }

    const int b = bh / NH, h = bh % NH;
#pragma unroll
    for (int i = 0; i < 8; i++) {
        int l = m0 + ty * 8 + i;
        size_t rowoff = ((size_t)(b * LLEN + l)) * DMODEL + h * 64;
#pragma unroll
        for (int j = 0; j < 4; j++)
            g_ctx[rowoff + tx * 4 + j] = acc[i][j];
    }
}

// =========================================================================
// Kernel 5: output projection.  proj = ctx @ W_O.  [8192,1024]x[1024,1024].
// =========================================================================
__global__ void proj_gemm_kernel(const float* __restrict__ Wo)
{
    __shared__ float As[8][132];
    __shared__ float Bs[8][132];

    const int tid = threadIdx.x;
    const int tx = tid & 15;
    const int ty = tid >> 4;
    const int n0 = blockIdx.x * 128;
    const int m0 = blockIdx.y * 128;

    float acc[8][8];
#pragma unroll
    for (int i = 0; i < 8; i++)
#pragma unroll
        for (int j = 0; j < 8; j++) acc[i][j] = 0.f;

    for (int k0 = 0; k0 < DMODEL; k0 += 8) {
#pragma unroll
        for (int r = 0; r < 4; r++) {
            int idx = tid + r * 256;
            int m = idx >> 3, k = idx & 7;
            As[k][m] = g_ctx[(size_t)(m0 + m) * DMODEL + k0 + k];
            int kb = idx >> 7, n = idx & 127;
            Bs[kb][n] = Wo[(size_t)(k0 + kb) * DMODEL + n0 + n];
        }
        __syncthreads();
#pragma unroll
        for (int kk = 0; kk < 8; kk++) {
            float a[8], bv[8];
#pragma unroll
            for (int i = 0; i < 8; i++) a[i] = As[kk][ty * 8 + i];
#pragma unroll
            for (int j = 0; j < 8; j++) bv[j] = Bs[kk][tx * 8 + j];
#pragma unroll
            for (int i = 0; i < 8; i++)
#pragma unroll
                for (int j = 0; j < 8; j++) acc[i][j] += a[i] * bv[j];
        }
        __syncthreads();
    }

#pragma unroll
    for (int i = 0; i < 8; i++) {
        int m = m0 + ty * 8 + i;
#pragma unroll
        for (int j = 0; j < 8; j++)
            g_proj[(size_t)m * DMODEL + n0 + tx * 8 + j] = acc[i][j];
    }
}

// =========================================================================
// Kernel 6: residual + LayerNorm.  out = LN(proj + X) * gamma + beta.
// One block (256 threads) per row of 1024.
// =========================================================================
__global__ void ln_kernel(const float* __restrict__ X,
                          const float* __restrict__ gamma,
                          const float* __restrict__ beta,
                          float* __restrict__ out)
{
    const int row = blockIdx.x;
    const int tid = threadIdx.x;
    const float* __restrict__ pr = g_proj + (size_t)row * DMODEL;
    const float* __restrict__ xr = X + (size_t)row * DMODEL;

    float4 p = reinterpret_cast<const float4*>(pr)[tid];
    float4 x = reinterpret_cast<const float4*>(xr)[tid];
    float y0 = p.x + x.x, y1 = p.y + x.y, y2 = p.z + x.z, y3 = p.w + x.w;

    __shared__ float red[8];
    // mean
    float s = y0 + y1 + y2 + y3;
#pragma unroll
    for (int o = 16; o > 0; o >>= 1) s += __shfl_xor_sync(0xffffffffu, s, o);
    if ((tid & 31) == 0) red[tid >> 5] = s;
    __syncthreads();
    float tot = red[0];
#pragma unroll
    for (int w = 1; w < 8; w++) tot += red[w];
    const float mu = tot * (1.0f / DMODEL);
    __syncthreads();

    // variance
    float d0 = y0 - mu, d1 = y1 - mu, d2 = y2 - mu, d3 = y3 - mu;
    float sq = d0 * d0 + d1 * d1 + d2 * d2 + d3 * d3;
#pragma unroll
    for (int o = 16; o > 0; o >>= 1) sq += __shfl_xor_sync(0xffffffffu, sq, o);
    if ((tid & 31) == 0) red[tid >> 5] = sq;
    __syncthreads();
    float tot2 = red[0];
#pragma unroll
    for (int w = 1; w < 8; w++) tot2 += red[w];
    const float var = tot2 * (1.0f / DMODEL);
    const float inv = rsqrtf(var + 1e-6f);

    const int c = tid * 4;
    float* __restrict__ orow = out + (size_t)row * DMODEL;
    orow[c + 0] = d0 * inv * gamma[c + 0] + beta[c + 0];
    orow[c + 1] = d1 * inv * gamma[c + 1] + beta[c + 1];
    orow[c + 2] = d2 * inv * gamma[c + 2] + beta[c + 2];
    orow[c + 3] = d3 * inv * gamma[c + 3] + beta[c + 3];
}

// =========================================================================
extern "C" void kernel_launch(void* const* d_in, const int* in_sizes, int n_in,
                              void* d_out, int out_size)
{
    const float* X     = (const float*)d_in[0];
    const int*   mask  = (const int*)d_in[1];     // bool mask as int32
    const float* Wq    = (const float*)d_in[2];
    const float* Wk    = (const float*)d_in[3];
    const float* Wv    = (const float*)d_in[4];
    const float* Wo    = (const float*)d_in[5];
    const float* gamma = (const float*)d_in[6];
    const float* beta  = (const float*)d_in[7];
    float* out = (float*)d_out;

    const long long LN_N   = (long long)BB * LLEN * DMODEL;            // 8,388,608
    const long long ATTN_N = (long long)BB * NH * LLEN * LLEN;         // 134,217,728

    // If the output buffer holds (ln_out, attn), write attn directly into it;
    // otherwise use the static scratch buffer.
    float* attn_ptr = ((long long)out_size >= LN_N + ATTN_N) ? (out + LN_N) : nullptr;

    qkv_gemm_kernel<<<dim3(24, 64), 256>>>(X, Wq, Wk, Wv);
    scores_kernel<<<dim3(16, 16, BB * NH), 256>>>(mask, attn_ptr);
    softmax_kernel<<<dim3(BB * NH * LLEN), 256>>>(attn_ptr);
    pv_kernel<<<dim3(8, BB * NH), 256>>>(attn_ptr);
    proj_gemm_kernel<<<dim3(8, 64), 256>>>(Wo);
    ln_kernel<<<BB * LLEN, 256>>>(X, gamma, beta, out);
}

// round 2
// speedup vs baseline: 2.4239x; 2.4239x over previous
#include <cuda_runtime.h>
#include <math.h>

#define BB 8
#define LLEN 1024
#define DMODEL 1024
#define NH 16
#define DHEAD 64

// ---------------- static scratch (no allocations allowed) ----------------
static __device__ float g_Q[(size_t)BB * NH * LLEN * DHEAD];     // 32 MB
static __device__ float g_K[(size_t)BB * NH * LLEN * DHEAD];     // 32 MB
static __device__ float g_V[(size_t)BB * NH * LLEN * DHEAD];     // 32 MB
static __device__ float g_ctx[(size_t)BB * LLEN * DMODEL];       // 32 MB
static __device__ float g_proj[(size_t)BB * LLEN * DMODEL];      // 32 MB
static __device__ float g_attn[(size_t)BB * NH * LLEN * LLEN];   // 512 MB fallback

// ---------------- tf32 warp-MMA helpers ----------------
__device__ __forceinline__ unsigned f2tf32(float x) {
    unsigned r;
    asm("cvt.rna.tf32.f32 %0, %1;" : "=r"(r) : "f"(x));
    return r;
}

__device__ __forceinline__ void mma_tf32(float* d, const unsigned* a, const unsigned* b) {
    asm volatile(
        "mma.sync.aligned.m16n8k8.row.col.f32.tf32.tf32.f32 "
        "{%0,%1,%2,%3}, {%4,%5,%6,%7}, {%8,%9}, {%0,%1,%2,%3};\n"
        : "+f"(d[0]), "+f"(d[1]), "+f"(d[2]), "+f"(d[3])
        : "r"(a[0]), "r"(a[1]), "r"(a[2]), "r"(a[3]), "r"(b[0]), "r"(b[1]));
}

// =========================================================================
// Kernel 1: fused QKV projection (tf32 MMA).  Y = X @ [Wq|Wk|Wv] scattered
// into [B,H,L,d].  M=8192, N=3072, K=1024.  BM=BN=128, BK=32.
// 8 warps: 4(m) x 2(n), warp tile 32x64; mma m16n8k8: 2 mtiles x 8 ntiles.
// =========================================================================
__global__ __launch_bounds__(256) void qkv_mma_kernel(
    const float* __restrict__ X,
    const float* __restrict__ Wq,
    const float* __restrict__ Wk,
    const float* __restrict__ Wv)
{
    __shared__ unsigned As[128][36];   // [m][k]
    __shared__ unsigned Bs[128][36];   // [n][k] = W^T

    const int tid  = threadIdx.x;
    const int warp = tid >> 5, lane = tid & 31;
    const int wm = warp >> 1, wn = warp & 1;
    const int g = lane >> 2, t = lane & 3;

    const int m0 = blockIdx.y * 128;
    const int ng = blockIdx.x * 128;          // global col in [0,3072)
    const int wsel = ng >> 10;
    const int nl = ng & 1023;
    const float* __restrict__ W = (wsel == 0) ? Wq : (wsel == 1 ? Wk : Wv);

    float acc[2][8][4];
#pragma unroll
    for (int i = 0; i < 2; i++)
#pragma unroll
        for (int j = 0; j < 8; j++)
#pragma unroll
            for (int c = 0; c < 4; c++) acc[i][j][c] = 0.f;

    for (int k0 = 0; k0 < DMODEL; k0 += 32) {
        // A: 128x32 from X (row-major, contiguous k) — float4 loads
#pragma unroll
        for (int r = 0; r < 4; r++) {
            int idx = tid + r * 256;
            int m = idx >> 3, kq = (idx & 7) * 4;
            const float4 v = *(const float4*)&X[(size_t)(m0 + m) * DMODEL + k0 + kq];
            As[m][kq + 0] = f2tf32(v.x);
            As[m][kq + 1] = f2tf32(v.y);
            As[m][kq + 2] = f2tf32(v.z);
            As[m][kq + 3] = f2tf32(v.w);
        }
        // B: transpose of W[k][n] -> Bs[n][k], coalesced gmem reads
#pragma unroll
        for (int r = 0; r < 16; r++) {
            int idx = tid + r * 256;
            int k = idx >> 7, n = idx & 127;
            Bs[n][k] = f2tf32(W[(size_t)(k0 + k) * DMODEL + nl + n]);
        }
        __syncthreads();

#pragma unroll
        for (int ks = 0; ks < 32; ks += 8) {
            unsigned af[2][4], bf[8][2];
#pragma unroll
            for (int i = 0; i < 2; i++) {
                int mr = wm * 32 + i * 16;
                af[i][0] = As[mr + g][ks + t];
                af[i][1] = As[mr + g + 8][ks + t];
                af[i][2] = As[mr + g][ks + t + 4];
                af[i][3] = As[mr + g + 8][ks + t + 4];
            }
#pragma unroll
            for (int j = 0; j < 8; j++) {
                int nr = wn * 64 + j * 8;
                bf[j][0] = Bs[nr + g][ks + t];
                bf[j][1] = Bs[nr + g][ks + t + 4];
            }
#pragma unroll
            for (int i = 0; i < 2; i++)
#pragma unroll
                for (int j = 0; j < 8; j++) mma_tf32(acc[i][j], af[i], bf[j]);
        }
        __syncthreads();
    }

    float* __restrict__ dst = (wsel == 0) ? g_Q : (wsel == 1 ? g_K : g_V);
#pragma unroll
    for (int i = 0; i < 2; i++) {
        int r0 = m0 + wm * 32 + i * 16 + g;
        int b = r0 >> 10, l = r0 & 1023;
#pragma unroll
        for (int j = 0; j < 8; j++) {
            int cl = nl + wn * 64 + j * 8 + 2 * t;
            int h = cl >> 6, d = cl & 63;
            size_t base = ((size_t)(b * NH + h) * LLEN);
            float2 v0 = make_float2(acc[i][j][0], acc[i][j][1]);
            float2 v1 = make_float2(acc[i][j][2], acc[i][j][3]);
            *(float2*)&dst[(base + l) * DHEAD + d] = v0;
            *(float2*)&dst[(base + l + 8) * DHEAD + d] = v1;
        }
    }
}

// =========================================================================
// Kernel 2: scores (tf32 MMA).  S = Q K^T * scale, mask -> -1e9.
// Per (b,h): M=N=1024, K=64.  BM=BN=128, BK=32 (2 iters).
// =========================================================================
__global__ __launch_bounds__(256) void scores_mma_kernel(
    const int* __restrict__ mask,
    float* __restrict__ attn_ext)
{
    __shared__ unsigned As[128][36];   // Q [m][k]
    __shared__ unsigned Bs[128][36];   // K [n][k]  (already K-major)

    const int tid  = threadIdx.x;
    const int warp = tid >> 5, lane = tid & 31;
    const int wm = warp >> 1, wn = warp & 1;
    const int g = lane >> 2, t = lane & 3;

    const int bh = blockIdx.z;
    const int b  = bh / NH;
    const int m0 = blockIdx.y * 128;
    const int n0 = blockIdx.x * 128;
    const float* __restrict__ Q = g_Q + (size_t)bh * LLEN * DHEAD;
    const float* __restrict__ K = g_K + (size_t)bh * LLEN * DHEAD;

    float acc[2][8][4];
#pragma unroll
    for (int i = 0; i < 2; i++)
#pragma unroll
        for (int j = 0; j < 8; j++)
#pragma unroll
            for (int c = 0; c < 4; c++) acc[i][j][c] = 0.f;

    for (int k0 = 0; k0 < DHEAD; k0 += 32) {
#pragma unroll
        for (int r = 0; r < 4; r++) {
            int idx = tid + r * 256;
            int m = idx >> 3, kq = (idx & 7) * 4;
            float4 va = *(const float4*)&Q[(size_t)(m0 + m) * DHEAD + k0 + kq];
            As[m][kq + 0] = f2tf32(va.x);
            As[m][kq + 1] = f2tf32(va.y);
            As[m][kq + 2] = f2tf32(va.z);
            As[m][kq + 3] = f2tf32(va.w);
            float4 vb = *(const float4*)&K[(size_t)(n0 + m) * DHEAD + k0 + kq];
            Bs[m][kq + 0] = f2tf32(vb.x);
            Bs[m][kq + 1] = f2tf32(vb.y);
            Bs[m][kq + 2] = f2tf32(vb.z);
            Bs[m][kq + 3] = f2tf32(vb.w);
        }
        __syncthreads();

#pragma unroll
        for (int ks = 0; ks < 32; ks += 8) {
            unsigned af[2][4], bf[8][2];
#pragma unroll
            for (int i = 0; i < 2; i++) {
                int mr = wm * 32 + i * 16;
                af[i][0] = As[mr + g][ks + t];
                af[i][1] = As[mr + g + 8][ks + t];
                af[i][2] = As[mr + g][ks + t + 4];
                af[i][3] = As[mr + g + 8][ks + t + 4];
            }
#pragma unroll
            for (int j = 0; j < 8; j++) {
                int nr = wn * 64 + j * 8;
                bf[j][0] = Bs[nr + g][ks + t];
                bf[j][1] = Bs[nr + g][ks + t + 4];
            }
#pragma unroll
            for (int i = 0; i < 2; i++)
#pragma unroll
                for (int j = 0; j < 8; j++) mma_tf32(acc[i][j], af[i], bf[j]);
        }
        __syncthreads();
    }

    float* __restrict__ P = attn_ext ? attn_ext : g_attn;
    const float scale = 0.125f;
#pragma unroll
    for (int i = 0; i < 2; i++) {
        int q0 = m0 + wm * 32 + i * 16 + g;
#pragma unroll
        for (int j = 0; j < 8; j++) {
            int c = n0 + wn * 64 + j * 8 + 2 * t;
            {
                const int2 mk = *(const int2*)&mask[((size_t)b * LLEN + q0) * LLEN + c];
                float2 v;
                v.x = mk.x ? -1e9f : acc[i][j][0] * scale;
                v.y = mk.y ? -1e9f : acc[i][j][1] * scale;
                *(float2*)&P[((size_t)bh * LLEN + q0) * LLEN + c] = v;
            }
            {
                const int2 mk = *(const int2*)&mask[((size_t)b * LLEN + q0 + 8) * LLEN + c];
                float2 v;
                v.x = mk.x ? -1e9f : acc[i][j][2] * scale;
                v.y = mk.y ? -1e9f : acc[i][j][3] * scale;
                *(float2*)&P[((size_t)bh * LLEN + q0 + 8) * LLEN + c] = v;
            }
        }
    }
}

// =========================================================================
// Kernel 3: in-place row softmax (unchanged from R1).
// =========================================================================
__global__ void softmax_kernel(float* __restrict__ attn_ext)
{
    float* __restrict__ P = attn_ext ? attn_ext : g_attn;
    const size_t row = blockIdx.x;
    float* __restrict__ prow = P + row * LLEN;
    const int tid = threadIdx.x;

    float4 v = reinterpret_cast<float4*>(prow)[tid];
    float mx = fmaxf(fmaxf(v.x, v.y), fmaxf(v.z, v.w));

    __shared__ float red[8];
#pragma unroll
    for (int o = 16; o > 0; o >>= 1) mx = fmaxf(mx, __shfl_xor_sync(0xffffffffu, mx, o));
    if ((tid & 31) == 0) red[tid >> 5] = mx;
    __syncthreads();
    float m = red[0];
#pragma unroll
    for (int w = 1; w < 8; w++) m = fmaxf(m, red[w]);
    __syncthreads();

    v.x = expf(v.x - m); v.y = expf(v.y - m);
    v.z = expf(v.z - m); v.w = expf(v.w - m);
    float s = v.x + v.y + v.z + v.w;
#pragma unroll
    for (int o = 16; o > 0; o >>= 1) s += __shfl_xor_sync(0xffffffffu, s, o);
    if ((tid & 31) == 0) red[tid >> 5] = s;
    __syncthreads();
    float tot = red[0];
#pragma unroll
    for (int w = 1; w < 8; w++) tot += red[w];

    float inv = 1.0f / tot;
    v.x *= inv; v.y *= inv; v.z *= inv; v.w *= inv;
    reinterpret_cast<float4*>(prow)[tid] = v;
}

// =========================================================================
// Kernel 4: context = P @ V (tf32 MMA).  Per head M=1024, N=64, K=1024.
// BM=128, BN=64, BK=32.  8 warps: 4(m) x 2(n), warp tile 32x32.
// =========================================================================
__global__ __launch_bounds__(256) void pv_mma_kernel(const float* __restrict__ attn_ext)
{
    __shared__ unsigned As[128][36];   // P [m][k]
    __shared__ unsigned Bs[64][36];    // V^T [n][k]

    const int tid  = threadIdx.x;
    const int warp = tid >> 5, lane = tid & 31;
    const int wm = warp >> 1, wn = warp & 1;
    const int g = lane >> 2, t = lane & 3;

    const int bh = blockIdx.y;
    const int m0 = blockIdx.x * 128;
    const float* __restrict__ P =
        (attn_ext ? attn_ext : (const float*)g_attn) + (size_t)bh * LLEN * LLEN;
    const float* __restrict__ V = g_V + (size_t)bh * LLEN * DHEAD;

    float acc[2][4][4];
#pragma unroll
    for (int i = 0; i < 2; i++)
#pragma unroll
        for (int j = 0; j < 4; j++)
#pragma unroll
            for (int c = 0; c < 4; c++) acc[i][j][c] = 0.f;

    for (int k0 = 0; k0 < LLEN; k0 += 32) {
#pragma unroll
        for (int r = 0; r < 4; r++) {
            int idx = tid + r * 256;
            int m = idx >> 3, kq = (idx & 7) * 4;
            const float4 v = *(const float4*)&P[(size_t)(m0 + m) * LLEN + k0 + kq];
            As[m][kq + 0] = f2tf32(v.x);
            As[m][kq + 1] = f2tf32(v.y);
            As[m][kq + 2] = f2tf32(v.z);
            As[m][kq + 3] = f2tf32(v.w);
        }
#pragma unroll
        for (int r = 0; r < 8; r++) {
            int idx = tid + r * 256;
            int k = idx >> 6, n = idx & 63;
            Bs[n][k] = f2tf32(V[(size_t)(k0 + k) * DHEAD + n]);
        }
        __syncthreads();

#pragma unroll
        for (int ks = 0; ks < 32; ks += 8) {
            unsigned af[2][4], bf[4][2];
#pragma unroll
            for (int i = 0; i < 2; i++) {
                int mr = wm * 32 + i * 16;
                af[i][0] = As[mr + g][ks + t];
                af[i][1] = As[mr + g + 8][ks + t];
                af[i][2] = As[mr + g][ks + t + 4];
                af[i][3] = As[mr + g + 8][ks + t + 4];
            }
#pragma unroll
            for (int j = 0; j < 4; j++) {
                int nr = wn * 32 + j * 8;
                bf[j][0] = Bs[nr + g][ks + t];
                bf[j][1] = Bs[nr + g][ks + t + 4];
            }
#pragma unroll
            for (int i = 0; i < 2; i++)
#pragma unroll
                for (int j = 0; j < 4; j++) mma_tf32(acc[i][j], af[i], bf[j]);
        }
        __syncthreads();
    }

    const int b = bh / NH, h = bh % NH;
#pragma unroll
    for (int i = 0; i < 2; i++) {
        int l0 = m0 + wm * 32 + i * 16 + g;
#pragma unroll
        for (int j = 0; j < 4; j++) {
            int d = wn * 32 + j * 8 + 2 * t;
            float2 v0 = make_float2(acc[i][j][0], acc[i][j][1]);
            float2 v1 = make_float2(acc[i][j][2], acc[i][j][3]);
            *(float2*)&g_ctx[((size_t)(b * LLEN + l0)) * DMODEL + h * 64 + d] = v0;
            *(float2*)&g_ctx[((size_t)(b * LLEN + l0 + 8)) * DMODEL + h * 64 + d] = v1;
        }
    }
}

// =========================================================================
// Kernel 5: output projection (tf32 MMA).  proj = ctx @ W_O.
// M=8192, N=1024, K=1024.  Same structure as qkv.
// =========================================================================
__global__ __launch_bounds__(256) void proj_mma_kernel(const float* __restrict__ Wo)
{
    __shared__ unsigned As[128][36];
    __shared__ unsigned Bs[128][36];

    const int tid  = threadIdx.x;
    const int warp = tid >> 5, lane = tid & 31;
    const int wm = warp >> 1, wn = warp & 1;
    const int g = lane >> 2, t = lane & 3;

    const int m0 = blockIdx.y * 128;
    const int n0 = blockIdx.x * 128;

    float acc[2][8][4];
#pragma unroll
    for (int i = 0; i < 2; i++)
#pragma unroll
        for (int j = 0; j < 8; j++)
#pragma unroll
            for (int c = 0; c < 4; c++) acc[i][j][c] = 0.f;

    for (int k0 = 0; k0 < DMODEL; k0 += 32) {
#pragma unroll
        for (int r = 0; r < 4; r++) {
            int idx = tid + r * 256;
            int m = idx >> 3, kq = (idx & 7) * 4;
            const float4 v = *(const float4*)&g_ctx[(size_t)(m0 + m) * DMODEL + k0 + kq];
            As[m][kq + 0] = f2tf32(v.x);
            As[m][kq + 1] = f2tf32(v.y);
            As[m][kq + 2] = f2tf32(v.z);
            As[m][kq + 3] = f2tf32(v.w);
        }
#pragma unroll
        for (int r = 0; r < 16; r++) {
            int idx = tid + r * 256;
            int k = idx >> 7, n = idx & 127;
            Bs[n][k] = f2tf32(Wo[(size_t)(k0 + k) * DMODEL + n0 + n]);
        }
        __syncthreads();

#pragma unroll
        for (int ks = 0; ks < 32; ks += 8) {
            unsigned af[2][4], bf[8][2];
#pragma unroll
            for (int i = 0; i < 2; i++) {
                int mr = wm * 32 + i * 16;
                af[i][0] = As[mr + g][ks + t];
                af[i][1] = As[mr + g + 8][ks + t];
                af[i][2] = As[mr + g][ks + t + 4];
                af[i][3] = As[mr + g + 8][ks + t + 4];
            }
#pragma unroll
            for (int j = 0; j < 8; j++) {
                int nr = wn * 64 + j * 8;
                bf[j][0] = Bs[nr + g][ks + t];
                bf[j][1] = Bs[nr + g][ks + t + 4];
            }
#pragma unroll
            for (int i = 0; i < 2; i++)
#pragma unroll
                for (int j = 0; j < 8; j++) mma_tf32(acc[i][j], af[i], bf[j]);
        }
        __syncthreads();
    }

#pragma unroll
    for (int i = 0; i < 2; i++) {
        int r0 = m0 + wm * 32 + i * 16 + g;
#pragma unroll
        for (int j = 0; j < 8; j++) {
            int c = n0 + wn * 64 + j * 8 + 2 * t;
            float2 v0 = make_float2(acc[i][j][0], acc[i][j][1]);
            float2 v1 = make_float2(acc[i][j][2], acc[i][j][3]);
            *(float2*)&g_proj[(size_t)r0 * DMODEL + c] = v0;
            *(float2*)&g_proj[(size_t)(r0 + 8) * DMODEL + c] = v1;
        }
    }
}

// =========================================================================
// Kernel 6: residual + LayerNorm (unchanged from R1).
// =========================================================================
__global__ void ln_kernel(const float* __restrict__ X,
                          const float* __restrict__ gamma,
                          const float* __restrict__ beta,
                          float* __restrict__ out)
{
    const int row = blockIdx.x;
    const int tid = threadIdx.x;
    const float* __restrict__ pr = g_proj + (size_t)row * DMODEL;
    const float* __restrict__ xr = X + (size_t)row * DMODEL;

    float4 p = reinterpret_cast<const float4*>(pr)[tid];
    float4 x = reinterpret_cast<const float4*>(xr)[tid];
    float y0 = p.x + x.x, y1 = p.y + x.y, y2 = p.z + x.z, y3 = p.w + x.w;

    __shared__ float red[8];
    float s = y0 + y1 + y2 + y3;
#pragma unroll
    for (int o = 16; o > 0; o >>= 1) s += __shfl_xor_sync(0xffffffffu, s, o);
    if ((tid & 31) == 0) red[tid >> 5] = s;
    __syncthreads();
    float tot = red[0];
#pragma unroll
    for (int w = 1; w < 8; w++) tot += red[w];
    const float mu = tot * (1.0f / DMODEL);
    __syncthreads();

    float d0 = y0 - mu, d1 = y1 - mu, d2 = y2 - mu, d3 = y3 - mu;
    float sq = d0 * d0 + d1 * d1 + d2 * d2 + d3 * d3;
#pragma unroll
    for (int o = 16; o > 0; o >>= 1) sq += __shfl_xor_sync(0xffffffffu, sq, o);
    if ((tid & 31) == 0) red[tid >> 5] = sq;
    __syncthreads();
    float tot2 = red[0];
#pragma unroll
    for (int w = 1; w < 8; w++) tot2 += red[w];
    const float var = tot2 * (1.0f / DMODEL);
    const float inv = rsqrtf(var + 1e-6f);

    const int c = tid * 4;
    float* __restrict__ orow = out + (size_t)row * DMODEL;
    orow[c + 0] = d0 * inv * gamma[c + 0] + beta[c + 0];
    orow[c + 1] = d1 * inv * gamma[c + 1] + beta[c + 1];
    orow[c + 2] = d2 * inv * gamma[c + 2] + beta[c + 2];
    orow[c + 3] = d3 * inv * gamma[c + 3] + beta[c + 3];
}

// =========================================================================
extern "C" void kernel_launch(void* const* d_in, const int* in_sizes, int n_in,
                              void* d_out, int out_size)
{
    const float* X     = (const float*)d_in[0];
    const int*   mask  = (const int*)d_in[1];
    const float* Wq    = (const float*)d_in[2];
    const float* Wk    = (const float*)d_in[3];
    const float* Wv    = (const float*)d_in[4];
    const float* Wo    = (const float*)d_in[5];
    const float* gamma = (const float*)d_in[6];
    const float* beta  = (const float*)d_in[7];
    float* out = (float*)d_out;

    const long long LN_N   = (long long)BB * LLEN * DMODEL;
    const long long ATTN_N = (long long)BB * NH * LLEN * LLEN;
    float* attn_ptr = ((long long)out_size >= LN_N + ATTN_N) ? (out + LN_N) : nullptr;

    qkv_mma_kernel<<<dim3(24, 64), 256>>>(X, Wq, Wk, Wv);
    scores_mma_kernel<<<dim3(8, 8, BB * NH), 256>>>(mask, attn_ptr);
    softmax_kernel<<<dim3(BB * NH * LLEN), 256>>>(attn_ptr);
    pv_mma_kernel<<<dim3(8, BB * NH), 256>>>(attn_ptr);
    proj_mma_kernel<<<dim3(8, 64), 256>>>(Wo);
    ln_kernel<<<BB * LLEN, 256>>>(X, gamma, beta, out);
}

// round 3
// speedup vs baseline: 2.4896x; 1.0271x over previous
#include <cuda_runtime.h>
#include <math.h>

#define BB 8
#define LLEN 1024
#define DMODEL 1024
#define NH 16
#define DHEAD 64

// ---------------- static scratch (no allocations allowed) ----------------
static __device__ float g_Q[(size_t)BB * NH * LLEN * DHEAD];     // 32 MB
static __device__ float g_K[(size_t)BB * NH * LLEN * DHEAD];     // 32 MB
static __device__ float g_V[(size_t)BB * NH * LLEN * DHEAD];     // 32 MB
static __device__ float g_ctx[(size_t)BB * LLEN * DMODEL];       // 32 MB
static __device__ float g_proj[(size_t)BB * LLEN * DMODEL];      // 32 MB
static __device__ float g_attn[(size_t)BB * NH * LLEN * LLEN];   // 512 MB fallback

// ---------------- tf32 warp-MMA helpers ----------------
__device__ __forceinline__ unsigned f2tf32(float x) {
    unsigned r;
    asm("cvt.rna.tf32.f32 %0, %1;" : "=r"(r) : "f"(x));
    return r;
}

__device__ __forceinline__ void mma_tf32(float* d, const unsigned* a, const unsigned* b) {
    asm volatile(
        "mma.sync.aligned.m16n8k8.row.col.f32.tf32.tf32.f32 "
        "{%0,%1,%2,%3}, {%4,%5,%6,%7}, {%8,%9}, {%0,%1,%2,%3};\n"
        : "+f"(d[0]), "+f"(d[1]), "+f"(d[2]), "+f"(d[3])
        : "r"(a[0]), "r"(a[1]), "r"(a[2]), "r"(a[3]), "r"(b[0]), "r"(b[1]));
}

__device__ __forceinline__ void cp16(void* smem_dst, const void* gsrc) {
    unsigned s = (unsigned)__cvta_generic_to_shared(smem_dst);
    asm volatile("cp.async.ca.shared.global [%0], [%1], 16;\n" :: "r"(s), "l"(gsrc));
}
__device__ __forceinline__ void cp_commit() {
    asm volatile("cp.async.commit_group;\n");
}
template <int N>
__device__ __forceinline__ void cp_wait() {
    asm volatile("cp.async.wait_group %0;\n" :: "n"(N));
}

// =========================================================================
// Kernel 1: fused QKV projection (tf32 MMA).  unchanged from R2.
// =========================================================================
__global__ __launch_bounds__(256) void qkv_mma_kernel(
    const float* __restrict__ X,
    const float* __restrict__ Wq,
    const float* __restrict__ Wk,
    const float* __restrict__ Wv)
{
    __shared__ unsigned As[128][36];
    __shared__ unsigned Bs[128][36];

    const int tid  = threadIdx.x;
    const int warp = tid >> 5, lane = tid & 31;
    const int wm = warp >> 1, wn = warp & 1;
    const int g = lane >> 2, t = lane & 3;

    const int m0 = blockIdx.y * 128;
    const int ng = blockIdx.x * 128;
    const int wsel = ng >> 10;
    const int nl = ng & 1023;
    const float* __restrict__ W = (wsel == 0) ? Wq : (wsel == 1 ? Wk : Wv);

    float acc[2][8][4];
#pragma unroll
    for (int i = 0; i < 2; i++)
#pragma unroll
        for (int j = 0; j < 8; j++)
#pragma unroll
            for (int c = 0; c < 4; c++) acc[i][j][c] = 0.f;

    for (int k0 = 0; k0 < DMODEL; k0 += 32) {
#pragma unroll
        for (int r = 0; r < 4; r++) {
            int idx = tid + r * 256;
            int m = idx >> 3, kq = (idx & 7) * 4;
            const float4 v = *(const float4*)&X[(size_t)(m0 + m) * DMODEL + k0 + kq];
            As[m][kq + 0] = f2tf32(v.x);
            As[m][kq + 1] = f2tf32(v.y);
            As[m][kq + 2] = f2tf32(v.z);
            As[m][kq + 3] = f2tf32(v.w);
        }
#pragma unroll
        for (int r = 0; r < 16; r++) {
            int idx = tid + r * 256;
            int k = idx >> 7, n = idx & 127;
            Bs[n][k] = f2tf32(W[(size_t)(k0 + k) * DMODEL + nl + n]);
        }
        __syncthreads();

#pragma unroll
        for (int ks = 0; ks < 32; ks += 8) {
            unsigned af[2][4], bf[8][2];
#pragma unroll
            for (int i = 0; i < 2; i++) {
                int mr = wm * 32 + i * 16;
                af[i][0] = As[mr + g][ks + t];
                af[i][1] = As[mr + g + 8][ks + t];
                af[i][2] = As[mr + g][ks + t + 4];
                af[i][3] = As[mr + g + 8][ks + t + 4];
            }
#pragma unroll
            for (int j = 0; j < 8; j++) {
                int nr = wn * 64 + j * 8;
                bf[j][0] = Bs[nr + g][ks + t];
                bf[j][1] = Bs[nr + g][ks + t + 4];
            }
#pragma unroll
            for (int i = 0; i < 2; i++)
#pragma unroll
                for (int j = 0; j < 8; j++) mma_tf32(acc[i][j], af[i], bf[j]);
        }
        __syncthreads();
    }

    float* __restrict__ dst = (wsel == 0) ? g_Q : (wsel == 1 ? g_K : g_V);
#pragma unroll
    for (int i = 0; i < 2; i++) {
        int r0 = m0 + wm * 32 + i * 16 + g;
        int b = r0 >> 10, l = r0 & 1023;
#pragma unroll
        for (int j = 0; j < 8; j++) {
            int cl = nl + wn * 64 + j * 8 + 2 * t;
            int h = cl >> 6, d = cl & 63;
            size_t base = ((size_t)(b * NH + h) * LLEN);
            float2 v0 = make_float2(acc[i][j][0], acc[i][j][1]);
            float2 v1 = make_float2(acc[i][j][2], acc[i][j][3]);
            *(float2*)&dst[(base + l) * DHEAD + d] = v0;
            *(float2*)&dst[(base + l + 8) * DHEAD + d] = v1;
        }
    }
}

// =========================================================================
// Kernel 2: FUSED scores + mask + softmax.  One CTA computes a 16-row x
// 1024-col strip of S = QK^T*scale for one (b,h), holds it in registers
// (8 warps x 128 cols each), does row softmax via quad-shuffle + smem
// cross-warp reduction, writes normalized P exactly once.
// =========================================================================
__global__ __launch_bounds__(256) void fused_attn_kernel(
    const int* __restrict__ mask,
    float* __restrict__ attn_ext)
{
    __shared__ unsigned Qs[16][68];
    __shared__ unsigned Ks[128][68];
    __shared__ float red[16][8];

    const int tid  = threadIdx.x;
    const int warp = tid >> 5, lane = tid & 31;
    const int g = lane >> 2, t = lane & 3;

    const int bh = blockIdx.y;
    const int b  = bh / NH;
    const int m0 = blockIdx.x * 16;
    const float* __restrict__ Q = g_Q + (size_t)bh * LLEN * DHEAD;
    const float* __restrict__ K = g_K + (size_t)bh * LLEN * DHEAD;

    // load Q strip 16x64 (one float4 per thread)
    {
        int m = tid >> 4, kq = (tid & 15) * 4;
        const float4 v = *(const float4*)&Q[(size_t)(m0 + m) * DHEAD + kq];
        Qs[m][kq + 0] = f2tf32(v.x);
        Qs[m][kq + 1] = f2tf32(v.y);
        Qs[m][kq + 2] = f2tf32(v.z);
        Qs[m][kq + 3] = f2tf32(v.w);
    }

    float acc[8][2][4];
#pragma unroll
    for (int s = 0; s < 8; s++)
#pragma unroll
        for (int j = 0; j < 2; j++)
#pragma unroll
            for (int c = 0; c < 4; c++) acc[s][j][c] = 0.f;

#pragma unroll
    for (int s = 0; s < 8; s++) {
        const int n0 = s * 128;
        __syncthreads();   // Qs visible (s=0) / previous MMA done (s>0)
#pragma unroll
        for (int r = 0; r < 8; r++) {
            int idx = tid + r * 256;
            int n = idx >> 4, kq = (idx & 15) * 4;
            const float4 v = *(const float4*)&K[(size_t)(n0 + n) * DHEAD + kq];
            Ks[n][kq + 0] = f2tf32(v.x);
            Ks[n][kq + 1] = f2tf32(v.y);
            Ks[n][kq + 2] = f2tf32(v.z);
            Ks[n][kq + 3] = f2tf32(v.w);
        }
        __syncthreads();

#pragma unroll
        for (int ks = 0; ks < 64; ks += 8) {
            unsigned af[4], bf[2][2];
            af[0] = Qs[g][ks + t];
            af[1] = Qs[g + 8][ks + t];
            af[2] = Qs[g][ks + t + 4];
            af[3] = Qs[g + 8][ks + t + 4];
#pragma unroll
            for (int j = 0; j < 2; j++) {
                int nr = warp * 16 + j * 8;
                bf[j][0] = Ks[nr + g][ks + t];
                bf[j][1] = Ks[nr + g][ks + t + 4];
            }
#pragma unroll
            for (int j = 0; j < 2; j++) mma_tf32(acc[s][j], af, bf[j]);
        }
    }

    // ---- scale + mask + row max ----
    const float scale = 0.125f;
    const int ql = m0 + g, qh = m0 + g + 8;
    const int* __restrict__ mrl = mask + ((size_t)b * LLEN + ql) * LLEN;
    const int* __restrict__ mrh = mask + ((size_t)b * LLEN + qh) * LLEN;

    float mxl = -3e38f, mxh = -3e38f;
#pragma unroll
    for (int s = 0; s < 8; s++)
#pragma unroll
        for (int j = 0; j < 2; j++) {
            const int col = s * 128 + warp * 16 + j * 8 + 2 * t;
            const int2 mkl = *(const int2*)&mrl[col];
            const int2 mkh = *(const int2*)&mrh[col];
            float* a = acc[s][j];
            a[0] = mkl.x ? -1e9f : a[0] * scale;
            a[1] = mkl.y ? -1e9f : a[1] * scale;
            a[2] = mkh.x ? -1e9f : a[2] * scale;
            a[3] = mkh.y ? -1e9f : a[3] * scale;
            mxl = fmaxf(mxl, fmaxf(a[0], a[1]));
            mxh = fmaxf(mxh, fmaxf(a[2], a[3]));
        }
    // quad reduce (lanes 4g+t, t varies -> xor 1,2)
    mxl = fmaxf(mxl, __shfl_xor_sync(0xffffffffu, mxl, 1));
    mxl = fmaxf(mxl, __shfl_xor_sync(0xffffffffu, mxl, 2));
    mxh = fmaxf(mxh, __shfl_xor_sync(0xffffffffu, mxh, 1));
    mxh = fmaxf(mxh, __shfl_xor_sync(0xffffffffu, mxh, 2));
    __syncthreads();   // retire previous red use (none) / MMA smem reads done
    if (t == 0) { red[g][warp] = mxl; red[g + 8][warp] = mxh; }
    __syncthreads();
    float Ml = red[g][0], Mh = red[g + 8][0];
#pragma unroll
    for (int w = 1; w < 8; w++) {
        Ml = fmaxf(Ml, red[g][w]);
        Mh = fmaxf(Mh, red[g + 8][w]);
    }
    __syncthreads();   // everyone has read maxes before red is reused

    // ---- exp + row sum ----
    float sl = 0.f, sh = 0.f;
#pragma unroll
    for (int s = 0; s < 8; s++)
#pragma unroll
        for (int j = 0; j < 2; j++) {
            float* a = acc[s][j];
            a[0] = expf(a[0] - Ml);
            a[1] = expf(a[1] - Ml);
            a[2] = expf(a[2] - Mh);
            a[3] = expf(a[3] - Mh);
            sl += a[0] + a[1];
            sh += a[2] + a[3];
        }
    sl += __shfl_xor_sync(0xffffffffu, sl, 1);
    sl += __shfl_xor_sync(0xffffffffu, sl, 2);
    sh += __shfl_xor_sync(0xffffffffu, sh, 1);
    sh += __shfl_xor_sync(0xffffffffu, sh, 2);
    if (t == 0) { red[g][warp] = sl; red[g + 8][warp] = sh; }
    __syncthreads();
    float Sl = 0.f, Sh = 0.f;
#pragma unroll
    for (int w = 0; w < 8; w++) { Sl += red[g][w]; Sh += red[g + 8][w]; }
    const float invl = 1.0f / Sl, invh = 1.0f / Sh;

    // ---- normalized write (single pass over P) ----
    float* __restrict__ P = attn_ext ? attn_ext : g_attn;
    float* __restrict__ prl = P + ((size_t)bh * LLEN + ql) * LLEN;
    float* __restrict__ prh = P + ((size_t)bh * LLEN + qh) * LLEN;
#pragma unroll
    for (int s = 0; s < 8; s++)
#pragma unroll
        for (int j = 0; j < 2; j++) {
            const int col = s * 128 + warp * 16 + j * 8 + 2 * t;
            const float* a = acc[s][j];
            *(float2*)&prl[col] = make_float2(a[0] * invl, a[1] * invl);
            *(float2*)&prh[col] = make_float2(a[2] * invh, a[3] * invh);
        }
}

// =========================================================================
// Kernel 3: context = P @ V (tf32 MMA, cp.async 2-stage pipeline).
// Per head M=1024, N=64, K=1024.  BM=128, BN=64, BK=16.
// =========================================================================
__global__ __launch_bounds__(256) void pv_mma_kernel(const float* __restrict__ attn_ext)
{
    __shared__ float Ps[2][128][20];
    __shared__ float Vs[2][16][72];

    const int tid  = threadIdx.x;
    const int warp = tid >> 5, lane = tid & 31;
    const int wm = warp >> 1, wn = warp & 1;
    const int g = lane >> 2, t = lane & 3;

    const int bh = blockIdx.y;
    const int m0 = blockIdx.x * 128;
    const float* __restrict__ P =
        (attn_ext ? attn_ext : (const float*)g_attn) + (size_t)bh * LLEN * LLEN;
    const float* __restrict__ V = g_V + (size_t)bh * LLEN * DHEAD;

    const int prow = tid >> 2, pc4 = (tid & 3) * 4;        // P: rows 0..63 (r=0), 64..127 (r=1)
    const int vrow = tid >> 4, vc4 = (tid & 15) * 4;       // V: 16x64

    float acc[2][4][4];
#pragma unroll
    for (int i = 0; i < 2; i++)
#pragma unroll
        for (int j = 0; j < 4; j++)
#pragma unroll
            for (int c = 0; c < 4; c++) acc[i][j][c] = 0.f;

    // prologue: stage 0
    {
        cp16(&Ps[0][prow][pc4],      &P[(size_t)(m0 + prow) * LLEN + pc4]);
        cp16(&Ps[0][prow + 64][pc4], &P[(size_t)(m0 + prow + 64) * LLEN + pc4]);
        cp16(&Vs[0][vrow][vc4],      &V[(size_t)vrow * DHEAD + vc4]);
        cp_commit();
    }

    const int NIT = LLEN / 16;
    for (int it = 0; it < NIT; it++) {
        const int buf = it & 1;
        if (it + 1 < NIT) {
            const int k0 = (it + 1) * 16;
            cp16(&Ps[buf ^ 1][prow][pc4],      &P[(size_t)(m0 + prow) * LLEN + k0 + pc4]);
            cp16(&Ps[buf ^ 1][prow + 64][pc4], &P[(size_t)(m0 + prow + 64) * LLEN + k0 + pc4]);
            cp16(&Vs[buf ^ 1][vrow][vc4],      &V[(size_t)(k0 + vrow) * DHEAD + vc4]);
            cp_commit();
            cp_wait<1>();
        } else {
            cp_wait<0>();
        }
        __syncthreads();

#pragma unroll
        for (int ks = 0; ks < 16; ks += 8) {
            unsigned af[2][4], bf[4][2];
#pragma unroll
            for (int i = 0; i < 2; i++) {
                int mr = wm * 32 + i * 16;
                af[i][0] = f2tf32(Ps[buf][mr + g][ks + t]);
                af[i][1] = f2tf32(Ps[buf][mr + g + 8][ks + t]);
                af[i][2] = f2tf32(Ps[buf][mr + g][ks + t + 4]);
                af[i][3] = f2tf32(Ps[buf][mr + g + 8][ks + t + 4]);
            }
#pragma unroll
            for (int j = 0; j < 4; j++) {
                int nr = wn * 32 + j * 8;
                bf[j][0] = f2tf32(Vs[buf][ks + t][nr + g]);
                bf[j][1] = f2tf32(Vs[buf][ks + t + 4][nr + g]);
            }
#pragma unroll
            for (int i = 0; i < 2; i++)
#pragma unroll
                for (int j = 0; j < 4; j++) mma_tf32(acc[i][j], af[i], bf[j]);
        }
        __syncthreads();
    }

    const int b = bh / NH, h = bh % NH;
#pragma unroll
    for (int i = 0; i < 2; i++) {
        int l0 = m0 + wm * 32 + i * 16 + g;
#pragma unroll
        for (int j = 0; j < 4; j++) {
            int d = wn * 32 + j * 8 + 2 * t;
            float2 v0 = make_float2(acc[i][j][0], acc[i][j][1]);
            float2 v1 = make_float2(acc[i][j][2], acc[i][j][3]);
            *(float2*)&g_ctx[((size_t)(b * LLEN + l0)) * DMODEL + h * 64 + d] = v0;
            *(float2*)&g_ctx[((size_t)(b * LLEN + l0 + 8)) * DMODEL + h * 64 + d] = v1;
        }
    }
}

// =========================================================================
// Kernel 4: output projection (tf32 MMA).  unchanged from R2.
// =========================================================================
__global__ __launch_bounds__(256) void proj_mma_kernel(const float* __restrict__ Wo)
{
    __shared__ unsigned As[128][36];
    __shared__ unsigned Bs[128][36];

    const int tid  = threadIdx.x;
    const int warp = tid >> 5, lane = tid & 31;
    const int wm = warp >> 1, wn = warp & 1;
    const int g = lane >> 2, t = lane & 3;

    const int m0 = blockIdx.y * 128;
    const int n0 = blockIdx.x * 128;

    float acc[2][8][4];
#pragma unroll
    for (int i = 0; i < 2; i++)
#pragma unroll
        for (int j = 0; j < 8; j++)
#pragma unroll
            for (int c = 0; c < 4; c++) acc[i][j][c] = 0.f;

    for (int k0 = 0; k0 < DMODEL; k0 += 32) {
#pragma unroll
        for (int r = 0; r < 4; r++) {
            int idx = tid + r * 256;
            int m = idx >> 3, kq = (idx & 7) * 4;
            const float4 v = *(const float4*)&g_ctx[(size_t)(m0 + m) * DMODEL + k0 + kq];
            As[m][kq + 0] = f2tf32(v.x);
            As[m][kq + 1] = f2tf32(v.y);
            As[m][kq + 2] = f2tf32(v.z);
            As[m][kq + 3] = f2tf32(v.w);
        }
#pragma unroll
        for (int r = 0; r < 16; r++) {
            int idx = tid + r * 256;
            int k = idx >> 7, n = idx & 127;
            Bs[n][k] = f2tf32(Wo[(size_t)(k0 + k) * DMODEL + n0 + n]);
        }
        __syncthreads();

#pragma unroll
        for (int ks = 0; ks < 32; ks += 8) {
            unsigned af[2][4], bf[8][2];
#pragma unroll
            for (int i = 0; i < 2; i++) {
                int mr = wm * 32 + i * 16;
                af[i][0] = As[mr + g][ks + t];
                af[i][1] = As[mr + g + 8][ks + t];
                af[i][2] = As[mr + g][ks + t + 4];
                af[i][3] = As[mr + g + 8][ks + t + 4];
            }
#pragma unroll
            for (int j = 0; j < 8; j++) {
                int nr = wn * 64 + j * 8;
                bf[j][0] = Bs[nr + g][ks + t];
                bf[j][1] = Bs[nr + g][ks + t + 4];
            }
#pragma unroll
            for (int i = 0; i < 2; i++)
#pragma unroll
                for (int j = 0; j < 8; j++) mma_tf32(acc[i][j], af[i], bf[j]);
        }
        __syncthreads();
    }

#pragma unroll
    for (int i = 0; i < 2; i++) {
        int r0 = m0 + wm * 32 + i * 16 + g;
#pragma unroll
        for (int j = 0; j < 8; j++) {
            int c = n0 + wn * 64 + j * 8 + 2 * t;
            float2 v0 = make_float2(acc[i][j][0], acc[i][j][1]);
            float2 v1 = make_float2(acc[i][j][2], acc[i][j][3]);
            *(float2*)&g_proj[(size_t)r0 * DMODEL + c] = v0;
            *(float2*)&g_proj[(size_t)(r0 + 8) * DMODEL + c] = v1;
        }
    }
}

// =========================================================================
// Kernel 5: residual + LayerNorm (unchanged).
// =========================================================================
__global__ void ln_kernel(const float* __restrict__ X,
                          const float* __restrict__ gamma,
                          const float* __restrict__ beta,
                          float* __restrict__ out)
{
    const int row = blockIdx.x;
    const int tid = threadIdx.x;
    const float* __restrict__ pr = g_proj + (size_t)row * DMODEL;
    const float* __restrict__ xr = X + (size_t)row * DMODEL;

    float4 p = reinterpret_cast<const float4*>(pr)[tid];
    float4 x = reinterpret_cast<const float4*>(xr)[tid];
    float y0 = p.x + x.x, y1 = p.y + x.y, y2 = p.z + x.z, y3 = p.w + x.w;

    __shared__ float red[8];
    float s = y0 + y1 + y2 + y3;
#pragma unroll
    for (int o = 16; o > 0; o >>= 1) s += __shfl_xor_sync(0xffffffffu, s, o);
    if ((tid & 31) == 0) red[tid >> 5] = s;
    __syncthreads();
    float tot = red[0];
#pragma unroll
    for (int w = 1; w < 8; w++) tot += red[w];
    const float mu = tot * (1.0f / DMODEL);
    __syncthreads();

    float d0 = y0 - mu, d1 = y1 - mu, d2 = y2 - mu, d3 = y3 - mu;
    float sq = d0 * d0 + d1 * d1 + d2 * d2 + d3 * d3;
#pragma unroll
    for (int o = 16; o > 0; o >>= 1) sq += __shfl_xor_sync(0xffffffffu, sq, o);
    if ((tid & 31) == 0) red[tid >> 5] = sq;
    __syncthreads();
    float tot2 = red[0];
#pragma unroll
    for (int w = 1; w < 8; w++) tot2 += red[w];
    const float var = tot2 * (1.0f / DMODEL);
    const float inv = rsqrtf(var + 1e-6f);

    const int c = tid * 4;
    float* __restrict__ orow = out + (size_t)row * DMODEL;
    orow[c + 0] = d0 * inv * gamma[c + 0] + beta[c + 0];
    orow[c + 1] = d1 * inv * gamma[c + 1] + beta[c + 1];
    orow[c + 2] = d2 * inv * gamma[c + 2] + beta[c + 2];
    orow[c + 3] = d3 * inv * gamma[c + 3] + beta[c + 3];
}

// =========================================================================
extern "C" void kernel_launch(void* const* d_in, const int* in_sizes, int n_in,
                              void* d_out, int out_size)
{
    const float* X     = (const float*)d_in[0];
    const int*   mask  = (const int*)d_in[1];
    const float* Wq    = (const float*)d_in[2];
    const float* Wk    = (const float*)d_in[3];
    const float* Wv    = (const float*)d_in[4];
    const float* Wo    = (const float*)d_in[5];
    const float* gamma = (const float*)d_in[6];
    const float* beta  = (const float*)d_in[7];
    float* out = (float*)d_out;

    const long long LN_N   = (long long)BB * LLEN * DMODEL;
    const long long ATTN_N = (long long)BB * NH * LLEN * LLEN;
    float* attn_ptr = ((long long)out_size >= LN_N + ATTN_N) ? (out + LN_N) : nullptr;

    qkv_mma_kernel<<<dim3(24, 64), 256>>>(X, Wq, Wk, Wv);
    fused_attn_kernel<<<dim3(64, BB * NH), 256>>>(mask, attn_ptr);
    pv_mma_kernel<<<dim3(8, BB * NH), 256>>>(attn_ptr);
    proj_mma_kernel<<<dim3(8, 64), 256>>>(Wo);
    ln_kernel<<<BB * LLEN, 256>>>(X, gamma, beta, out);
}